// round 15
// baseline (speedup 1.0000x reference)
#include <cuda_runtime.h>
#include <cuda_fp16.h>
#include <stdint.h>
#include <math.h>

#define R 40000
#define RB 313
#define R2 (RB*128)      // 40064 padded rows
#define EMAX 500000
#define NBIN 10
#define HN 8
#define CAP 64           // bucket capacity per node (Poisson mean 12.5; P(>64)~0)

// ---------------- scratch (zero at module load; g_deg re-zeroed per node in attn1) ----
__device__ __half g_embh [R2*64];   // fp16 embeddings (tail rows stay zero)
__device__ float  g_ahead[R2*64];
__device__ __half g_attwh[R2*128];  // per col-pair: [at half2 | wt half2]
__device__ float  g_res  [R2*64];
__device__ int    g_deg  [R];       // must be 0 on entry
__device__ int    g_etb  [R*CAP];   // bucketed edges: tail | (bin<<20)

__device__ __forceinline__ float lk(float x) { return x > 0.f ? x : 0.2f * x; }
__device__ __forceinline__ int clampi(int v, int lo, int hi) { return min(max(v, lo), hi); }

// ---------------- side stream (created at module load) ----------------
struct StreamHolder {
    cudaStream_t s;
    cudaEvent_t fork, join;
    StreamHolder() {
        cudaStreamCreateWithFlags(&s, cudaStreamNonBlocking);
        cudaEventCreateWithFlags(&fork, cudaEventDisableTiming);
        cudaEventCreateWithFlags(&join, cudaEventDisableTiming);
    }
};
static StreamHolder g_sh;

// ---------------- edge bucketing: ONE pass, no hist/scan ----------------
__global__ void scatter_kernel(const int* __restrict__ trip, int E) {
    int i = blockIdx.x * blockDim.x + threadIdx.x;
    int e0 = i * 4;
    if (e0 + 3 < E) {
        int4 a = ((const int4*)trip)[i * 3];
        int4 b = ((const int4*)trip)[i * 3 + 1];
        int4 c = ((const int4*)trip)[i * 3 + 2];
        int h0 = clampi(a.x, 0, R-1), t0 = clampi(a.y, 0, R-1), b0 = clampi(a.z, 0, NBIN-1);
        int h1 = clampi(a.w, 0, R-1), t1 = clampi(b.x, 0, R-1), b1 = clampi(b.y, 0, NBIN-1);
        int h2 = clampi(b.z, 0, R-1), t2 = clampi(b.w, 0, R-1), b2 = clampi(c.x, 0, NBIN-1);
        int h3 = clampi(c.y, 0, R-1), t3 = clampi(c.z, 0, R-1), b3 = clampi(c.w, 0, NBIN-1);
        int p0 = atomicAdd(&g_deg[h0], 1);
        int p1 = atomicAdd(&g_deg[h1], 1);
        int p2 = atomicAdd(&g_deg[h2], 1);
        int p3 = atomicAdd(&g_deg[h3], 1);
        if (p0 < CAP) g_etb[h0 * CAP + p0] = t0 | (b0 << 20);
        if (p1 < CAP) g_etb[h1 * CAP + p1] = t1 | (b1 << 20);
        if (p2 < CAP) g_etb[h2 * CAP + p2] = t2 | (b2 << 20);
        if (p3 < CAP) g_etb[h3 * CAP + p3] = t3 | (b3 << 20);
    } else {
        for (int e = e0; e < E; e++) {
            int h = clampi(trip[e * 3], 0, R - 1);
            int t = clampi(trip[e * 3 + 1], 0, R - 1);
            int b = clampi(trip[e * 3 + 2], 0, NBIN - 1);
            int p = atomicAdd(&g_deg[h], 1);
            if (p < CAP) g_etb[h * CAP + p] = t | (b << 20);
        }
    }
}

// ---------------- HMMA helpers ----------------
__device__ __forceinline__ void ldsm_x4(unsigned& r0, unsigned& r1, unsigned& r2, unsigned& r3,
                                        const __half* p) {
    unsigned a = (unsigned)__cvta_generic_to_shared(p);
    asm volatile("ldmatrix.sync.aligned.m8n8.x4.shared.b16 {%0,%1,%2,%3}, [%4];"
        : "=r"(r0), "=r"(r1), "=r"(r2), "=r"(r3) : "r"(a));
}
__device__ __forceinline__ void ldsm_x4t(unsigned& r0, unsigned& r1, unsigned& r2, unsigned& r3,
                                         const __half* p) {
    unsigned a = (unsigned)__cvta_generic_to_shared(p);
    asm volatile("ldmatrix.sync.aligned.m8n8.x4.trans.shared.b16 {%0,%1,%2,%3}, [%4];"
        : "=r"(r0), "=r"(r1), "=r"(r2), "=r"(r3) : "r"(a));
}
__device__ __forceinline__ void mma16816(float c[4],
                                         unsigned a0, unsigned a1, unsigned a2, unsigned a3,
                                         unsigned b0, unsigned b1) {
    asm volatile("mma.sync.aligned.m16n8k16.row.col.f32.f16.f16.f32 "
        "{%0,%1,%2,%3}, {%4,%5,%6,%7}, {%8,%9}, {%0,%1,%2,%3};"
        : "+f"(c[0]), "+f"(c[1]), "+f"(c[2]), "+f"(c[3])
        : "r"(a0), "r"(a1), "r"(a2), "r"(a3), "r"(b0), "r"(b1));
}

#define SPITCH 72   // smem pitch in halfs: conflict-free for ldmatrix

__device__ __forceinline__ void cvt8(__half* dst, float4 w) {
    ((__half2*)dst)[0] = __floats2half2_rn(w.x, w.y);
    ((__half2*)dst)[1] = __floats2half2_rn(w.z, w.w);
}

// dual-matrix mainloop: D[m][128x64] += A[128x64] @ W[m][64x64]
__device__ __forceinline__ void mma_dual(float c[2][8][4], const __half* sA,
                                         const __half* sW0, const __half* sW1,
                                         int warpm, int lane) {
    int ar = lane & 15, ac = (lane >> 4) * 8;
    #pragma unroll
    for (int k = 0; k < 4; k++) {
        unsigned a0, a1, a2, a3;
        ldsm_x4(a0, a1, a2, a3, &sA[(warpm + ar) * SPITCH + k * 16 + ac]);
        #pragma unroll
        for (int np = 0; np < 4; np++) {
            unsigned b0, b1, b2, b3;
            ldsm_x4t(b0, b1, b2, b3, &sW0[(k * 16 + ar) * SPITCH + np * 16 + ac]);
            mma16816(c[0][np * 2],     a0, a1, a2, a3, b0, b1);
            mma16816(c[0][np * 2 + 1], a0, a1, a2, a3, b2, b3);
            ldsm_x4t(b0, b1, b2, b3, &sW1[(k * 16 + ar) * SPITCH + np * 16 + ac]);
            mma16816(c[1][np * 2],     a0, a1, a2, a3, b0, b1);
            mma16816(c[1][np * 2 + 1], a0, a1, a2, a3, b2, b3);
        }
    }
}

__device__ __forceinline__ void mma_one(float c[8][4], const __half* sA,
                                        const __half* sW0, int warpm, int lane) {
    int ar = lane & 15, ac = (lane >> 4) * 8;
    #pragma unroll
    for (int k = 0; k < 4; k++) {
        unsigned a0, a1, a2, a3;
        ldsm_x4(a0, a1, a2, a3, &sA[(warpm + ar) * SPITCH + k * 16 + ac]);
        #pragma unroll
        for (int np = 0; np < 4; np++) {
            unsigned b0, b1, b2, b3;
            ldsm_x4t(b0, b1, b2, b3, &sW0[(k * 16 + ar) * SPITCH + np * 16 + ac]);
            mma16816(c[np * 2],     a0, a1, a2, a3, b0, b1);
            mma16816(c[np * 2 + 1], a0, a1, a2, a3, b2, b3);
        }
    }
}

// ---------------- fused GEMM per layer (HMMA): 256 thr, 128-row tile ----------
// X0 != null (layer 0): pre-pass computes sA = relu(fp16(X0_tile) @ IW + ib).
__global__ __launch_bounds__(256, 2) void gemm4_kernel(
    const float* __restrict__ PW,    // 128x64 (head | tail)
    const float* __restrict__ AW,    // 64x64
    const float* __restrict__ RW,    // 64x64
    const float* __restrict__ pb,
    const float* __restrict__ ab,
    const float* __restrict__ rbv,
    const float* __restrict__ X0,
    const float* __restrict__ IW,
    const float* __restrict__ ib) {
    __shared__ __half sA[128 * SPITCH];     // 18.0 KB
    __shared__ __half sW[2][64 * SPITCH];   // 18.0 KB
    int t = threadIdx.x;
    int lane = t & 31, warp = t >> 5;
    int warpm = warp * 16;
    int base = blockIdx.x * 128;
    int lq = lane & 3, lr = lane >> 2;

    if (X0) {
        // load rel_emb tile (fp32, guarded) -> fp16 sA; IW -> sW[0]
        #pragma unroll
        for (int i = 0; i < 8; i++) {
            int id = t + i * 256;             // 2048 float4
            int row = id >> 4, c4 = id & 15;
            int gr = base + row;
            float4 w = (gr < R) ? ((const float4*)X0)[(size_t)gr * 16 + c4]
                                : make_float4(0.f, 0.f, 0.f, 0.f);
            cvt8(&sA[row * SPITCH + c4 * 4], w);
        }
        #pragma unroll
        for (int i = 0; i < 4; i++) {
            int id = t + i * 256;             // 1024 float4
            int row = id >> 4, c4 = id & 15;
            cvt8(&sW[0][row * SPITCH + c4 * 4], ((const float4*)IW)[id]);
        }
        __syncthreads();
        float c[8][4] = {};
        mma_one(c, sA, sW[0], warpm, lane);
        __syncthreads();   // all ldmatrix reads of sA done
        #pragma unroll
        for (int n = 0; n < 8; n++) {
            int col = n * 8 + lq * 2;
            float2 bi = ((const float2*)ib)[col >> 1];
            int r0 = warpm + lr;
            ((__half2*)&sA[r0 * SPITCH + col])[0] =
                __floats2half2_rn(fmaxf(c[n][0] + bi.x, 0.f), fmaxf(c[n][1] + bi.y, 0.f));
            ((__half2*)&sA[(r0 + 8) * SPITCH + col])[0] =
                __floats2half2_rn(fmaxf(c[n][2] + bi.x, 0.f), fmaxf(c[n][3] + bi.y, 0.f));
        }
        __syncthreads();
    } else {
        // load fp16 emb tile directly
        #pragma unroll
        for (int i = 0; i < 4; i++) {
            int id = t + i * 256;             // 1024 uint4 (8 halfs each)
            int row = id >> 3, c8 = id & 7;
            *(uint4*)&sA[row * SPITCH + c8 * 8] =
                ((const uint4*)g_embh)[(size_t)base * 8 + id];
        }
    }
    // load PW: rows 0-63 -> sW[0], rows 64-127 -> sW[1]
    #pragma unroll
    for (int i = 0; i < 8; i++) {
        int id = t + i * 256;                 // 2048 float4 = 128 rows
        int row = id >> 4, c4 = id & 15;
        float4 w = ((const float4*)PW)[id];
        __half* d = (row < 64) ? &sW[0][row * SPITCH + c4 * 4]
                               : &sW[1][(row - 64) * SPITCH + c4 * 4];
        cvt8(d, w);
    }
    __syncthreads();

    __half2* H = (__half2*)g_attwh;

    // ---- pass 0: ahead (fp32, no bias) + atail (+pb, fp16 slot 0) ----
    {
        float c[2][8][4] = {};
        mma_dual(c, sA, sW[0], sW[1], warpm, lane);
        #pragma unroll
        for (int n = 0; n < 8; n++) {
            int col = n * 8 + lq * 2;
            size_t r0 = base + warpm + lr, r1 = r0 + 8;
            *(float2*)&g_ahead[r0 * 64 + col] = make_float2(c[0][n][0], c[0][n][1]);
            *(float2*)&g_ahead[r1 * 64 + col] = make_float2(c[0][n][2], c[0][n][3]);
            float2 bt = ((const float2*)pb)[col >> 1];
            H[r0 * 64 + col] = __floats2half2_rn(c[1][n][0] + bt.x, c[1][n][1] + bt.y);
            H[r1 * 64 + col] = __floats2half2_rn(c[1][n][2] + bt.x, c[1][n][3] + bt.y);
        }
    }
    __syncthreads();   // done reading sW
    // load AW -> sW[0], RW -> sW[1]
    #pragma unroll
    for (int i = 0; i < 4; i++) {
        int id = t + i * 256;
        int row = id >> 4, c4 = id & 15;
        cvt8(&sW[0][row * SPITCH + c4 * 4], ((const float4*)AW)[id]);
        cvt8(&sW[1][row * SPITCH + c4 * 4], ((const float4*)RW)[id]);
    }
    __syncthreads();
    // ---- pass 1: wtail (+ab, fp16 slot 1) + res (relu(+rb), fp32) ----
    {
        float c[2][8][4] = {};
        mma_dual(c, sA, sW[0], sW[1], warpm, lane);
        #pragma unroll
        for (int n = 0; n < 8; n++) {
            int col = n * 8 + lq * 2;
            size_t r0 = base + warpm + lr, r1 = r0 + 8;
            float2 ba = ((const float2*)ab)[col >> 1];
            float2 br = ((const float2*)rbv)[col >> 1];
            H[r0 * 64 + col + 1] = __floats2half2_rn(c[0][n][0] + ba.x, c[0][n][1] + ba.y);
            H[r1 * 64 + col + 1] = __floats2half2_rn(c[0][n][2] + ba.x, c[0][n][3] + ba.y);
            *(float2*)&g_res[r0 * 64 + col] =
                make_float2(fmaxf(c[1][n][0] + br.x, 0.f), fmaxf(c[1][n][1] + br.y, 0.f));
            *(float2*)&g_res[r1 * 64 + col] =
                make_float2(fmaxf(c[1][n][2] + br.x, 0.f), fmaxf(c[1][n][3] + br.y, 0.f));
        }
    }
}

// ---------------- attention: one warp per node, 4-deep batch, no-max softmax ----
// bucket layout: node r's edges at g_etb[r*CAP .. r*CAP+deg). attn1 (outp!=null)
// re-zeros g_deg[r] from its owning warp (single-thread load->store, no race).
__global__ void attn_kernel(const float* __restrict__ abin,
                            const float* __restrict__ avec,
                            float* outp) {
    __shared__ float s_abin[NBIN * HN];
    int t = threadIdx.x;
    if (t < NBIN * HN) s_abin[t] = lk(abin[t]);
    __syncthreads();

    int warp = t >> 5, lane = t & 31;
    int r = blockIdx.x * 8 + warp;
    if (r >= R) return;

    // lane 0 owns the deg read (and, in the final layer, the reset)
    int dg = 0;
    if (lane == 0) {
        dg = g_deg[r];
        if (outp) g_deg[r] = 0;   // safe: same thread, load precedes store
    }
    dg = __shfl_sync(0xffffffffu, dg, 0);
    if (dg > CAP) dg = CAP;

    int h = lane >> 2;
    float2 ahv = ((const float2*)g_ahead)[r * 32 + lane];
    float avx = avec[h * 8 + (lane & 3) * 2];
    float avy = avec[h * 8 + (lane & 3) * 2 + 1];
    const uint2* AWp = (const uint2*)g_attwh;

    float s = 0.f, a0 = 0.f, a1 = 0.f;
    int i = r * CAP, end = r * CAP + dg;

    while (i < end) {
        int n = end - i; if (n > 4) n = 4;
        uint2 v[4]; int bbs[4];
        #pragma unroll
        for (int j = 0; j < 4; j++) {
            if (j < n) {
                int etb = g_etb[i + j];
                bbs[j] = etb >> 20;
                v[j] = AWp[(size_t)(etb & 0xFFFFF) * 32 + lane];
            }
        }
        #pragma unroll
        for (int j = 0; j < 4; j++) {
            if (j < n) {
                float2 at = __half22float2(*(const __half2*)&v[j].x);
                float2 wt = __half22float2(*(const __half2*)&v[j].y);
                float z0 = lk(ahv.x + at.x);
                float z1 = lk(ahv.y + at.y);
                float p = z0 * avx + z1 * avy;
                p += __shfl_xor_sync(0xffffffffu, p, 1);
                p += __shfl_xor_sync(0xffffffffu, p, 2);
                float e = __expf(p + s_abin[bbs[j] * 8 + h]);
                s  += e;
                a0 += e * wt.x;
                a1 += e * wt.y;
            }
        }
        i += 4;
    }
    float inv = 1.f / (s + 1e-16f);
    float o0 = fmaxf(a0 * inv, 0.f);
    float o1 = fmaxf(a1 * inv, 0.f);
    float2 rv = ((const float2*)g_res)[r * 32 + lane];
    float ox = o0 + rv.x;
    float oy = o1 + rv.y;
    if (outp)
        ((float2*)outp)[r * 32 + lane] = make_float2(ox, oy);
    else
        ((__half2*)g_embh)[r * 32 + lane] = __floats2half2_rn(ox, oy);
}

// ---------------- host ----------------
extern "C" void kernel_launch(void* const* d_in, const int* in_sizes, int n_in,
                              void* d_out, int out_size) {
    const int*   trip     = (const int*)d_in[0];
    const float* rel_emb  = (const float*)d_in[1];
    const float* p1w      = (const float*)d_in[2];
    const float* p1b      = (const float*)d_in[3];
    const float* apw      = (const float*)d_in[4];
    const float* apb      = (const float*)d_in[5];
    const float* abin     = (const float*)d_in[6];
    const float* avec     = (const float*)d_in[7];
    const float* agw      = (const float*)d_in[8];
    const float* agb      = (const float*)d_in[9];
    const float* rw       = (const float*)d_in[10];
    const float* rb       = (const float*)d_in[11];

    int E = in_sizes[0] / 3;
    if (E > EMAX) E = EMAX;

    const int TB = 256;
    int e4bl = ((E + 3) / 4 + TB - 1) / TB;

    // fork: single-pass edge bucketing on side stream, concurrent with layer-0 GEMM
    cudaEventRecord(g_sh.fork, 0);
    cudaStreamWaitEvent(g_sh.s, g_sh.fork, 0);
    scatter_kernel<<<e4bl, TB, 0, g_sh.s>>>(trip, E);
    cudaEventRecord(g_sh.join, g_sh.s);

    // main stream: layer-0 GEMM (independent of edge buckets)
    gemm4_kernel<<<RB, 256>>>(apw, agw, rw, apb, agb, rb,
                              rel_emb, p1w, p1b);

    // join before first attention (needs buckets + gemm outputs)
    cudaStreamWaitEvent(0, g_sh.join, 0);
    attn_kernel<<<R / 8, 256>>>(abin, avec, nullptr);

    // layer 1
    gemm4_kernel<<<RB, 256>>>(apw + 8192, agw + 4096, rw + 4096,
                              apb + 64, agb + 64, rb + 64,
                              nullptr, nullptr, nullptr);
    attn_kernel<<<R / 8, 256>>>(abin + NBIN * HN, avec + HN * 8,
                                (float*)d_out);
}

// round 16
// speedup vs baseline: 1.2228x; 1.2228x over previous
#include <cuda_runtime.h>
#include <cuda_fp16.h>
#include <stdint.h>
#include <math.h>

#define R 40000
#define RB 313
#define R2 (RB*128)      // 40064 padded rows
#define EMAX 500000
#define NBIN 10
#define HN 8
#define NSB 40           // scan blocks: ceil(40000/1024)
#define NWARPS 5000      // R / 8 nodes per warp

// ---------------- scratch (zero at module load; CSR re-zeroed each call) ----
__device__ __half g_embh [R2*64];   // fp16 embeddings (tail rows stay zero)
__device__ float  g_ahead[R2*64];
__device__ __half g_attwh[R2*128];  // per col-pair: [at half2 | wt half2]
__device__ float  g_res  [R2*64];
__device__ int    g_deg  [R];       // must be 0 on entry
__device__ int    g_off  [R+1];
__device__ int    g_cursor[R];
__device__ int    g_pub  [NSB];     // must be 0 on entry
__device__ int    g_etb  [EMAX];    // packed: tail | (bin<<20)

__device__ __forceinline__ float lk(float x) { return x > 0.f ? x : 0.2f * x; }
__device__ __forceinline__ int clampi(int v, int lo, int hi) { return min(max(v, lo), hi); }

// ---------------- side stream (created at module load) ----------------
struct StreamHolder {
    cudaStream_t s;
    cudaEvent_t fork, join;
    StreamHolder() {
        cudaStreamCreateWithFlags(&s, cudaStreamNonBlocking);
        cudaEventCreateWithFlags(&fork, cudaEventDisableTiming);
        cudaEventCreateWithFlags(&join, cudaEventDisableTiming);
    }
};
static StreamHolder g_sh;

// ---------------- CSR build ----------------
__global__ void hist_kernel(const int* __restrict__ trip, int E) {
    int i = blockIdx.x * blockDim.x + threadIdx.x;
    int e0 = i * 4;
    if (e0 + 3 < E) {
        int4 a = ((const int4*)trip)[i * 3];
        int4 b = ((const int4*)trip)[i * 3 + 1];
        int4 c = ((const int4*)trip)[i * 3 + 2];
        atomicAdd(&g_deg[clampi(a.x, 0, R - 1)], 1);
        atomicAdd(&g_deg[clampi(a.w, 0, R - 1)], 1);
        atomicAdd(&g_deg[clampi(b.z, 0, R - 1)], 1);
        atomicAdd(&g_deg[clampi(c.y, 0, R - 1)], 1);
    } else {
        for (int e = e0; e < E; e++)
            atomicAdd(&g_deg[clampi(trip[e * 3], 0, R - 1)], 1);
    }
}

__global__ void scan_kernel() {
    __shared__ int ws[8];
    __shared__ int s_bp;
    int t = threadIdx.x;
    int lane = t & 31, wid = t >> 5, b = blockIdx.x;
    int base = b * 1024 + t * 4;

    int d0 = (base + 0 < R) ? g_deg[base + 0] : 0;
    int d1 = (base + 1 < R) ? g_deg[base + 1] : 0;
    int d2 = (base + 2 < R) ? g_deg[base + 2] : 0;
    int d3 = (base + 3 < R) ? g_deg[base + 3] : 0;
    int v1 = d0 + d1, v2 = v1 + d2, v3 = v2 + d3;
    int tot = v3;
    int sc = tot;
    #pragma unroll
    for (int o = 1; o < 32; o <<= 1) {
        int n = __shfl_up_sync(0xffffffffu, sc, o);
        if (lane >= o) sc += n;
    }
    if (lane == 31) ws[wid] = sc;
    __syncthreads();
    if (wid == 0) {
        int x = (lane < 8) ? ws[lane] : 0;
        #pragma unroll
        for (int o = 1; o < 8; o <<= 1) {
            int n = __shfl_up_sync(0xffffffffu, x, o);
            if (lane >= o) x += n;
        }
        if (lane < 8) ws[lane] = x;
    }
    __syncthreads();
    int pre = sc - tot + (wid ? ws[wid - 1] : 0);

    if (t == 0) atomicExch(&g_pub[b], ws[7] + 1);

    if (wid == 0) {
        int sum = 0;
        for (int j = lane; j < b; j += 32) {
            int v;
            do { v = atomicAdd(&g_pub[j], 0); } while (v == 0);
            sum += v - 1;
        }
        #pragma unroll
        for (int o = 16; o > 0; o >>= 1) sum += __shfl_xor_sync(0xffffffffu, sum, o);
        if (lane == 0) s_bp = sum;
    }
    __syncthreads();
    int p = s_bp + pre;

    if (base + 0 < R) { g_off[base + 1] = p + d0; g_cursor[base + 0] = p; }
    if (base + 1 < R) { g_off[base + 2] = p + v1; g_cursor[base + 1] = p + d0; }
    if (base + 2 < R) { g_off[base + 3] = p + v2; g_cursor[base + 2] = p + v1; }
    if (base + 3 < R) { g_off[base + 4] = p + v3; g_cursor[base + 3] = p + v2; }
    if (b == 0 && t == 0) g_off[0] = 0;
}

__global__ void scatter_kernel(const int* __restrict__ trip, int E) {
    int i = blockIdx.x * blockDim.x + threadIdx.x;
    int e0 = i * 4;
    if (e0 + 3 < E) {
        int4 a = ((const int4*)trip)[i * 3];
        int4 b = ((const int4*)trip)[i * 3 + 1];
        int4 c = ((const int4*)trip)[i * 3 + 2];
        int h0 = clampi(a.x, 0, R-1), t0 = clampi(a.y, 0, R-1), b0 = clampi(a.z, 0, NBIN-1);
        int h1 = clampi(a.w, 0, R-1), t1 = clampi(b.x, 0, R-1), b1 = clampi(b.y, 0, NBIN-1);
        int h2 = clampi(b.z, 0, R-1), t2 = clampi(b.w, 0, R-1), b2 = clampi(c.x, 0, NBIN-1);
        int h3 = clampi(c.y, 0, R-1), t3 = clampi(c.z, 0, R-1), b3 = clampi(c.w, 0, NBIN-1);
        int p0 = atomicAdd(&g_cursor[h0], 1);
        int p1 = atomicAdd(&g_cursor[h1], 1);
        int p2 = atomicAdd(&g_cursor[h2], 1);
        int p3 = atomicAdd(&g_cursor[h3], 1);
        g_etb[p0] = t0 | (b0 << 20);
        g_etb[p1] = t1 | (b1 << 20);
        g_etb[p2] = t2 | (b2 << 20);
        g_etb[p3] = t3 | (b3 << 20);
    } else {
        for (int e = e0; e < E; e++) {
            int h = clampi(trip[e * 3], 0, R - 1);
            int t = clampi(trip[e * 3 + 1], 0, R - 1);
            int b = clampi(trip[e * 3 + 2], 0, NBIN - 1);
            int p = atomicAdd(&g_cursor[h], 1);
            g_etb[p] = t | (b << 20);
        }
    }
}

// ---------------- HMMA helpers ----------------
__device__ __forceinline__ void ldsm_x4(unsigned& r0, unsigned& r1, unsigned& r2, unsigned& r3,
                                        const __half* p) {
    unsigned a = (unsigned)__cvta_generic_to_shared(p);
    asm volatile("ldmatrix.sync.aligned.m8n8.x4.shared.b16 {%0,%1,%2,%3}, [%4];"
        : "=r"(r0), "=r"(r1), "=r"(r2), "=r"(r3) : "r"(a));
}
__device__ __forceinline__ void ldsm_x4t(unsigned& r0, unsigned& r1, unsigned& r2, unsigned& r3,
                                         const __half* p) {
    unsigned a = (unsigned)__cvta_generic_to_shared(p);
    asm volatile("ldmatrix.sync.aligned.m8n8.x4.trans.shared.b16 {%0,%1,%2,%3}, [%4];"
        : "=r"(r0), "=r"(r1), "=r"(r2), "=r"(r3) : "r"(a));
}
__device__ __forceinline__ void mma16816(float c[4],
                                         unsigned a0, unsigned a1, unsigned a2, unsigned a3,
                                         unsigned b0, unsigned b1) {
    asm volatile("mma.sync.aligned.m16n8k16.row.col.f32.f16.f16.f32 "
        "{%0,%1,%2,%3}, {%4,%5,%6,%7}, {%8,%9}, {%0,%1,%2,%3};"
        : "+f"(c[0]), "+f"(c[1]), "+f"(c[2]), "+f"(c[3])
        : "r"(a0), "r"(a1), "r"(a2), "r"(a3), "r"(b0), "r"(b1));
}

#define SPITCH 72   // smem pitch in halfs: conflict-free for ldmatrix

__device__ __forceinline__ void cvt8(__half* dst, float4 w) {
    ((__half2*)dst)[0] = __floats2half2_rn(w.x, w.y);
    ((__half2*)dst)[1] = __floats2half2_rn(w.z, w.w);
}

// dual-matrix mainloop: D[m][128x64] += A[128x64] @ W[m][64x64]
__device__ __forceinline__ void mma_dual(float c[2][8][4], const __half* sA,
                                         const __half* sW0, const __half* sW1,
                                         int warpm, int lane) {
    int ar = lane & 15, ac = (lane >> 4) * 8;
    #pragma unroll
    for (int k = 0; k < 4; k++) {
        unsigned a0, a1, a2, a3;
        ldsm_x4(a0, a1, a2, a3, &sA[(warpm + ar) * SPITCH + k * 16 + ac]);
        #pragma unroll
        for (int np = 0; np < 4; np++) {
            unsigned b0, b1, b2, b3;
            ldsm_x4t(b0, b1, b2, b3, &sW0[(k * 16 + ar) * SPITCH + np * 16 + ac]);
            mma16816(c[0][np * 2],     a0, a1, a2, a3, b0, b1);
            mma16816(c[0][np * 2 + 1], a0, a1, a2, a3, b2, b3);
            ldsm_x4t(b0, b1, b2, b3, &sW1[(k * 16 + ar) * SPITCH + np * 16 + ac]);
            mma16816(c[1][np * 2],     a0, a1, a2, a3, b0, b1);
            mma16816(c[1][np * 2 + 1], a0, a1, a2, a3, b2, b3);
        }
    }
}

__device__ __forceinline__ void mma_one(float c[8][4], const __half* sA,
                                        const __half* sW0, int warpm, int lane) {
    int ar = lane & 15, ac = (lane >> 4) * 8;
    #pragma unroll
    for (int k = 0; k < 4; k++) {
        unsigned a0, a1, a2, a3;
        ldsm_x4(a0, a1, a2, a3, &sA[(warpm + ar) * SPITCH + k * 16 + ac]);
        #pragma unroll
        for (int np = 0; np < 4; np++) {
            unsigned b0, b1, b2, b3;
            ldsm_x4t(b0, b1, b2, b3, &sW0[(k * 16 + ar) * SPITCH + np * 16 + ac]);
            mma16816(c[np * 2],     a0, a1, a2, a3, b0, b1);
            mma16816(c[np * 2 + 1], a0, a1, a2, a3, b2, b3);
        }
    }
}

// ---------------- fused GEMM per layer (HMMA): 256 thr, 128-row tile ----------
// X0 != null (layer 0): pre-pass computes sA = relu(fp16(X0_tile) @ IW + ib).
__global__ __launch_bounds__(256, 2) void gemm4_kernel(
    const float* __restrict__ PW,    // 128x64 (head | tail)
    const float* __restrict__ AW,    // 64x64
    const float* __restrict__ RW,    // 64x64
    const float* __restrict__ pb,
    const float* __restrict__ ab,
    const float* __restrict__ rbv,
    const float* __restrict__ X0,
    const float* __restrict__ IW,
    const float* __restrict__ ib) {
    __shared__ __half sA[128 * SPITCH];     // 18.0 KB
    __shared__ __half sW[2][64 * SPITCH];   // 18.0 KB
    int t = threadIdx.x;
    int lane = t & 31, warp = t >> 5;
    int warpm = warp * 16;
    int base = blockIdx.x * 128;
    int lq = lane & 3, lr = lane >> 2;

    if (X0) {
        // load rel_emb tile (fp32, guarded) -> fp16 sA; IW -> sW[0]
        #pragma unroll
        for (int i = 0; i < 8; i++) {
            int id = t + i * 256;             // 2048 float4
            int row = id >> 4, c4 = id & 15;
            int gr = base + row;
            float4 w = (gr < R) ? ((const float4*)X0)[(size_t)gr * 16 + c4]
                                : make_float4(0.f, 0.f, 0.f, 0.f);
            cvt8(&sA[row * SPITCH + c4 * 4], w);
        }
        #pragma unroll
        for (int i = 0; i < 4; i++) {
            int id = t + i * 256;             // 1024 float4
            int row = id >> 4, c4 = id & 15;
            cvt8(&sW[0][row * SPITCH + c4 * 4], ((const float4*)IW)[id]);
        }
        __syncthreads();
        float c[8][4] = {};
        mma_one(c, sA, sW[0], warpm, lane);
        __syncthreads();   // all ldmatrix reads of sA done
        #pragma unroll
        for (int n = 0; n < 8; n++) {
            int col = n * 8 + lq * 2;
            float2 bi = ((const float2*)ib)[col >> 1];
            int r0 = warpm + lr;
            ((__half2*)&sA[r0 * SPITCH + col])[0] =
                __floats2half2_rn(fmaxf(c[n][0] + bi.x, 0.f), fmaxf(c[n][1] + bi.y, 0.f));
            ((__half2*)&sA[(r0 + 8) * SPITCH + col])[0] =
                __floats2half2_rn(fmaxf(c[n][2] + bi.x, 0.f), fmaxf(c[n][3] + bi.y, 0.f));
        }
        __syncthreads();
    } else {
        // load fp16 emb tile directly
        #pragma unroll
        for (int i = 0; i < 4; i++) {
            int id = t + i * 256;             // 1024 uint4 (8 halfs each)
            int row = id >> 3, c8 = id & 7;
            *(uint4*)&sA[row * SPITCH + c8 * 8] =
                ((const uint4*)g_embh)[(size_t)base * 8 + id];
        }
    }
    // load PW: rows 0-63 -> sW[0], rows 64-127 -> sW[1]
    #pragma unroll
    for (int i = 0; i < 8; i++) {
        int id = t + i * 256;                 // 2048 float4 = 128 rows
        int row = id >> 4, c4 = id & 15;
        float4 w = ((const float4*)PW)[id];
        __half* d = (row < 64) ? &sW[0][row * SPITCH + c4 * 4]
                               : &sW[1][(row - 64) * SPITCH + c4 * 4];
        cvt8(d, w);
    }
    __syncthreads();

    __half2* H = (__half2*)g_attwh;

    // ---- pass 0: ahead (fp32, no bias) + atail (+pb, fp16 slot 0) ----
    {
        float c[2][8][4] = {};
        mma_dual(c, sA, sW[0], sW[1], warpm, lane);
        #pragma unroll
        for (int n = 0; n < 8; n++) {
            int col = n * 8 + lq * 2;
            size_t r0 = base + warpm + lr, r1 = r0 + 8;
            *(float2*)&g_ahead[r0 * 64 + col] = make_float2(c[0][n][0], c[0][n][1]);
            *(float2*)&g_ahead[r1 * 64 + col] = make_float2(c[0][n][2], c[0][n][3]);
            float2 bt = ((const float2*)pb)[col >> 1];
            H[r0 * 64 + col] = __floats2half2_rn(c[1][n][0] + bt.x, c[1][n][1] + bt.y);
            H[r1 * 64 + col] = __floats2half2_rn(c[1][n][2] + bt.x, c[1][n][3] + bt.y);
        }
    }
    __syncthreads();   // done reading sW
    // load AW -> sW[0], RW -> sW[1]
    #pragma unroll
    for (int i = 0; i < 4; i++) {
        int id = t + i * 256;
        int row = id >> 4, c4 = id & 15;
        cvt8(&sW[0][row * SPITCH + c4 * 4], ((const float4*)AW)[id]);
        cvt8(&sW[1][row * SPITCH + c4 * 4], ((const float4*)RW)[id]);
    }
    __syncthreads();
    // ---- pass 1: wtail (+ab, fp16 slot 1) + res (relu(+rb), fp32) ----
    {
        float c[2][8][4] = {};
        mma_dual(c, sA, sW[0], sW[1], warpm, lane);
        #pragma unroll
        for (int n = 0; n < 8; n++) {
            int col = n * 8 + lq * 2;
            size_t r0 = base + warpm + lr, r1 = r0 + 8;
            float2 ba = ((const float2*)ab)[col >> 1];
            float2 br = ((const float2*)rbv)[col >> 1];
            H[r0 * 64 + col + 1] = __floats2half2_rn(c[0][n][0] + ba.x, c[0][n][1] + ba.y);
            H[r1 * 64 + col + 1] = __floats2half2_rn(c[0][n][2] + ba.x, c[0][n][3] + ba.y);
            *(float2*)&g_res[r0 * 64 + col] =
                make_float2(fmaxf(c[1][n][0] + br.x, 0.f), fmaxf(c[1][n][1] + br.y, 0.f));
            *(float2*)&g_res[r1 * 64 + col] =
                make_float2(fmaxf(c[1][n][2] + br.x, 0.f), fmaxf(c[1][n][3] + br.y, 0.f));
        }
    }
}

// ---------------- attention: one warp per 8 nodes (imbalance averaging) -------
// grid = 625 blocks x 8 warps = 5000 warps; warp g handles r = g + k*5000.
__global__ void attn_kernel(const float* __restrict__ abin,
                            const float* __restrict__ avec,
                            float* outp) {
    __shared__ float s_abin[NBIN * HN];
    int t = threadIdx.x;
    if (t < NBIN * HN) s_abin[t] = lk(abin[t]);

    if (outp) {   // final layer: re-zero CSR scratch for next graph replay
        int g = blockIdx.x * blockDim.x + t;
        if (g < R) g_deg[g] = 0;
        if (g < NSB) g_pub[g] = 0;
    }
    __syncthreads();

    int warp = t >> 5, lane = t & 31;
    int wg = blockIdx.x * 8 + warp;   // 0..4999
    int h = lane >> 2;
    float avx = avec[h * 8 + (lane & 3) * 2];
    float avy = avec[h * 8 + (lane & 3) * 2 + 1];
    const uint2* AWp = (const uint2*)g_attwh;

    #pragma unroll 1
    for (int k = 0; k < 8; k++) {
        int r = wg + k * NWARPS;     // < 40000 always (5000*8 = R)
        float2 ahv = ((const float2*)g_ahead)[r * 32 + lane];

        float s = 0.f, a0 = 0.f, a1 = 0.f;
        int i = g_off[r], end = g_off[r + 1];

        while (i < end) {
            int n = end - i; if (n > 4) n = 4;
            uint2 v[4]; int bbs[4];
            #pragma unroll
            for (int j = 0; j < 4; j++) {
                if (j < n) {
                    int etb = g_etb[i + j];
                    bbs[j] = etb >> 20;
                    v[j] = AWp[(size_t)(etb & 0xFFFFF) * 32 + lane];
                }
            }
            #pragma unroll
            for (int j = 0; j < 4; j++) {
                if (j < n) {
                    float2 at = __half22float2(*(const __half2*)&v[j].x);
                    float2 wt = __half22float2(*(const __half2*)&v[j].y);
                    float z0 = lk(ahv.x + at.x);
                    float z1 = lk(ahv.y + at.y);
                    float p = z0 * avx + z1 * avy;
                    p += __shfl_xor_sync(0xffffffffu, p, 1);
                    p += __shfl_xor_sync(0xffffffffu, p, 2);
                    float e = __expf(p + s_abin[bbs[j] * 8 + h]);
                    s  += e;
                    a0 += e * wt.x;
                    a1 += e * wt.y;
                }
            }
            i += 4;
        }
        float inv = 1.f / (s + 1e-16f);
        float o0 = fmaxf(a0 * inv, 0.f);
        float o1 = fmaxf(a1 * inv, 0.f);
        float2 rv = ((const float2*)g_res)[r * 32 + lane];
        float ox = o0 + rv.x;
        float oy = o1 + rv.y;
        if (outp)
            ((float2*)outp)[r * 32 + lane] = make_float2(ox, oy);
        else
            ((__half2*)g_embh)[r * 32 + lane] = __floats2half2_rn(ox, oy);
    }
}

// ---------------- host ----------------
extern "C" void kernel_launch(void* const* d_in, const int* in_sizes, int n_in,
                              void* d_out, int out_size) {
    const int*   trip     = (const int*)d_in[0];
    const float* rel_emb  = (const float*)d_in[1];
    const float* p1w      = (const float*)d_in[2];
    const float* p1b      = (const float*)d_in[3];
    const float* apw      = (const float*)d_in[4];
    const float* apb      = (const float*)d_in[5];
    const float* abin     = (const float*)d_in[6];
    const float* avec     = (const float*)d_in[7];
    const float* agw      = (const float*)d_in[8];
    const float* agb      = (const float*)d_in[9];
    const float* rw       = (const float*)d_in[10];
    const float* rb       = (const float*)d_in[11];

    int E = in_sizes[0] / 3;
    if (E > EMAX) E = EMAX;

    const int TB = 256;
    int e4bl = ((E + 3) / 4 + TB - 1) / TB;

    // fork: CSR build on side stream, concurrent with layer-0 GEMM
    cudaEventRecord(g_sh.fork, 0);
    cudaStreamWaitEvent(g_sh.s, g_sh.fork, 0);
    hist_kernel<<<e4bl, TB, 0, g_sh.s>>>(trip, E);
    scan_kernel<<<NSB, 256, 0, g_sh.s>>>();
    scatter_kernel<<<e4bl, TB, 0, g_sh.s>>>(trip, E);
    cudaEventRecord(g_sh.join, g_sh.s);

    // main stream: layer-0 GEMM (independent of CSR)
    gemm4_kernel<<<RB, 256>>>(apw, agw, rw, apb, agb, rb,
                              rel_emb, p1w, p1b);

    // join before first attention (needs CSR + gemm outputs)
    cudaStreamWaitEvent(0, g_sh.join, 0);
    attn_kernel<<<NWARPS / 8, 256>>>(abin, avec, nullptr);

    // layer 1
    gemm4_kernel<<<RB, 256>>>(apw + 8192, agw + 4096, rw + 4096,
                              apb + 64, agb + 64, rb + 64,
                              nullptr, nullptr, nullptr);
    attn_kernel<<<NWARPS / 8, 256>>>(abin + NBIN * HN, avec + HN * 8,
                                     (float*)d_out);
}

// round 17
// speedup vs baseline: 1.5033x; 1.2294x over previous
#include <cuda_runtime.h>
#include <cuda_fp16.h>
#include <stdint.h>
#include <math.h>

#define R 40000
#define RB 626           // 64-row tiles over R2 rows
#define R2 (RB*64)       // 40064 padded rows
#define EMAX 500000
#define NBIN 10
#define HN 8
#define NSB 40           // scan blocks: ceil(40000/1024)

// ---------------- scratch (zero at module load; CSR re-zeroed each call) ----
__device__ __half g_embh [R2*64];   // fp16 embeddings (tail rows stay zero)
__device__ float  g_ahead[R2*64];
__device__ __half g_attwh[R2*128];  // per col-pair: [at half2 | wt half2]
__device__ float  g_res  [R2*64];
__device__ int    g_deg  [R];       // must be 0 on entry
__device__ int    g_off  [R+1];
__device__ int    g_cursor[R];
__device__ int    g_pub  [NSB];     // must be 0 on entry
__device__ int    g_etb  [EMAX];    // packed: tail | (bin<<20)

__device__ __forceinline__ float lk(float x) { return x > 0.f ? x : 0.2f * x; }
__device__ __forceinline__ int clampi(int v, int lo, int hi) { return min(max(v, lo), hi); }

// ---------------- side stream (created at module load) ----------------
struct StreamHolder {
    cudaStream_t s;
    cudaEvent_t fork, join;
    StreamHolder() {
        cudaStreamCreateWithFlags(&s, cudaStreamNonBlocking);
        cudaEventCreateWithFlags(&fork, cudaEventDisableTiming);
        cudaEventCreateWithFlags(&join, cudaEventDisableTiming);
    }
};
static StreamHolder g_sh;

// ---------------- CSR build ----------------
__global__ void hist_kernel(const int* __restrict__ trip, int E) {
    int i = blockIdx.x * blockDim.x + threadIdx.x;
    int e0 = i * 4;
    if (e0 + 3 < E) {
        int4 a = ((const int4*)trip)[i * 3];
        int4 b = ((const int4*)trip)[i * 3 + 1];
        int4 c = ((const int4*)trip)[i * 3 + 2];
        atomicAdd(&g_deg[clampi(a.x, 0, R - 1)], 1);
        atomicAdd(&g_deg[clampi(a.w, 0, R - 1)], 1);
        atomicAdd(&g_deg[clampi(b.z, 0, R - 1)], 1);
        atomicAdd(&g_deg[clampi(c.y, 0, R - 1)], 1);
    } else {
        for (int e = e0; e < E; e++)
            atomicAdd(&g_deg[clampi(trip[e * 3], 0, R - 1)], 1);
    }
}

__global__ void scan_kernel() {
    __shared__ int ws[8];
    __shared__ int s_bp;
    int t = threadIdx.x;
    int lane = t & 31, wid = t >> 5, b = blockIdx.x;
    int base = b * 1024 + t * 4;

    int d0 = (base + 0 < R) ? g_deg[base + 0] : 0;
    int d1 = (base + 1 < R) ? g_deg[base + 1] : 0;
    int d2 = (base + 2 < R) ? g_deg[base + 2] : 0;
    int d3 = (base + 3 < R) ? g_deg[base + 3] : 0;
    int v1 = d0 + d1, v2 = v1 + d2, v3 = v2 + d3;
    int tot = v3;
    int sc = tot;
    #pragma unroll
    for (int o = 1; o < 32; o <<= 1) {
        int n = __shfl_up_sync(0xffffffffu, sc, o);
        if (lane >= o) sc += n;
    }
    if (lane == 31) ws[wid] = sc;
    __syncthreads();
    if (wid == 0) {
        int x = (lane < 8) ? ws[lane] : 0;
        #pragma unroll
        for (int o = 1; o < 8; o <<= 1) {
            int n = __shfl_up_sync(0xffffffffu, x, o);
            if (lane >= o) x += n;
        }
        if (lane < 8) ws[lane] = x;
    }
    __syncthreads();
    int pre = sc - tot + (wid ? ws[wid - 1] : 0);

    if (t == 0) atomicExch(&g_pub[b], ws[7] + 1);

    if (wid == 0) {
        int sum = 0;
        for (int j = lane; j < b; j += 32) {
            int v;
            do { v = atomicAdd(&g_pub[j], 0); } while (v == 0);
            sum += v - 1;
        }
        #pragma unroll
        for (int o = 16; o > 0; o >>= 1) sum += __shfl_xor_sync(0xffffffffu, sum, o);
        if (lane == 0) s_bp = sum;
    }
    __syncthreads();
    int p = s_bp + pre;

    if (base + 0 < R) { g_off[base + 1] = p + d0; g_cursor[base + 0] = p; }
    if (base + 1 < R) { g_off[base + 2] = p + v1; g_cursor[base + 1] = p + d0; }
    if (base + 2 < R) { g_off[base + 3] = p + v2; g_cursor[base + 2] = p + v1; }
    if (base + 3 < R) { g_off[base + 4] = p + v3; g_cursor[base + 3] = p + v2; }
    if (b == 0 && t == 0) g_off[0] = 0;
}

__global__ void scatter_kernel(const int* __restrict__ trip, int E) {
    int i = blockIdx.x * blockDim.x + threadIdx.x;
    int e0 = i * 4;
    if (e0 + 3 < E) {
        int4 a = ((const int4*)trip)[i * 3];
        int4 b = ((const int4*)trip)[i * 3 + 1];
        int4 c = ((const int4*)trip)[i * 3 + 2];
        int h0 = clampi(a.x, 0, R-1), t0 = clampi(a.y, 0, R-1), b0 = clampi(a.z, 0, NBIN-1);
        int h1 = clampi(a.w, 0, R-1), t1 = clampi(b.x, 0, R-1), b1 = clampi(b.y, 0, NBIN-1);
        int h2 = clampi(b.z, 0, R-1), t2 = clampi(b.w, 0, R-1), b2 = clampi(c.x, 0, NBIN-1);
        int h3 = clampi(c.y, 0, R-1), t3 = clampi(c.z, 0, R-1), b3 = clampi(c.w, 0, NBIN-1);
        int p0 = atomicAdd(&g_cursor[h0], 1);
        int p1 = atomicAdd(&g_cursor[h1], 1);
        int p2 = atomicAdd(&g_cursor[h2], 1);
        int p3 = atomicAdd(&g_cursor[h3], 1);
        g_etb[p0] = t0 | (b0 << 20);
        g_etb[p1] = t1 | (b1 << 20);
        g_etb[p2] = t2 | (b2 << 20);
        g_etb[p3] = t3 | (b3 << 20);
    } else {
        for (int e = e0; e < E; e++) {
            int h = clampi(trip[e * 3], 0, R - 1);
            int t = clampi(trip[e * 3 + 1], 0, R - 1);
            int b = clampi(trip[e * 3 + 2], 0, NBIN - 1);
            int p = atomicAdd(&g_cursor[h], 1);
            g_etb[p] = t | (b << 20);
        }
    }
}

// ---------------- HMMA helpers ----------------
__device__ __forceinline__ void ldsm_x4(unsigned& r0, unsigned& r1, unsigned& r2, unsigned& r3,
                                        const __half* p) {
    unsigned a = (unsigned)__cvta_generic_to_shared(p);
    asm volatile("ldmatrix.sync.aligned.m8n8.x4.shared.b16 {%0,%1,%2,%3}, [%4];"
        : "=r"(r0), "=r"(r1), "=r"(r2), "=r"(r3) : "r"(a));
}
__device__ __forceinline__ void ldsm_x4t(unsigned& r0, unsigned& r1, unsigned& r2, unsigned& r3,
                                         const __half* p) {
    unsigned a = (unsigned)__cvta_generic_to_shared(p);
    asm volatile("ldmatrix.sync.aligned.m8n8.x4.trans.shared.b16 {%0,%1,%2,%3}, [%4];"
        : "=r"(r0), "=r"(r1), "=r"(r2), "=r"(r3) : "r"(a));
}
__device__ __forceinline__ void mma16816(float c[4],
                                         unsigned a0, unsigned a1, unsigned a2, unsigned a3,
                                         unsigned b0, unsigned b1) {
    asm volatile("mma.sync.aligned.m16n8k16.row.col.f32.f16.f16.f32 "
        "{%0,%1,%2,%3}, {%4,%5,%6,%7}, {%8,%9}, {%0,%1,%2,%3};"
        : "+f"(c[0]), "+f"(c[1]), "+f"(c[2]), "+f"(c[3])
        : "r"(a0), "r"(a1), "r"(a2), "r"(a3), "r"(b0), "r"(b1));
}

#define SPITCH 72   // smem pitch in halfs: conflict-free for ldmatrix

__device__ __forceinline__ void cvt8(__half* dst, float4 w) {
    ((__half2*)dst)[0] = __floats2half2_rn(w.x, w.y);
    ((__half2*)dst)[1] = __floats2half2_rn(w.z, w.w);
}

// dual-matrix mainloop: D[m][64x64] += A[64x64] @ W[m][64x64]  (4 warps, m16 each)
__device__ __forceinline__ void mma_dual(float c[2][8][4], const __half* sA,
                                         const __half* sW0, const __half* sW1,
                                         int warpm, int lane) {
    int ar = lane & 15, ac = (lane >> 4) * 8;
    #pragma unroll
    for (int k = 0; k < 4; k++) {
        unsigned a0, a1, a2, a3;
        ldsm_x4(a0, a1, a2, a3, &sA[(warpm + ar) * SPITCH + k * 16 + ac]);
        #pragma unroll
        for (int np = 0; np < 4; np++) {
            unsigned b0, b1, b2, b3;
            ldsm_x4t(b0, b1, b2, b3, &sW0[(k * 16 + ar) * SPITCH + np * 16 + ac]);
            mma16816(c[0][np * 2],     a0, a1, a2, a3, b0, b1);
            mma16816(c[0][np * 2 + 1], a0, a1, a2, a3, b2, b3);
            ldsm_x4t(b0, b1, b2, b3, &sW1[(k * 16 + ar) * SPITCH + np * 16 + ac]);
            mma16816(c[1][np * 2],     a0, a1, a2, a3, b0, b1);
            mma16816(c[1][np * 2 + 1], a0, a1, a2, a3, b2, b3);
        }
    }
}

__device__ __forceinline__ void mma_one(float c[8][4], const __half* sA,
                                        const __half* sW0, int warpm, int lane) {
    int ar = lane & 15, ac = (lane >> 4) * 8;
    #pragma unroll
    for (int k = 0; k < 4; k++) {
        unsigned a0, a1, a2, a3;
        ldsm_x4(a0, a1, a2, a3, &sA[(warpm + ar) * SPITCH + k * 16 + ac]);
        #pragma unroll
        for (int np = 0; np < 4; np++) {
            unsigned b0, b1, b2, b3;
            ldsm_x4t(b0, b1, b2, b3, &sW0[(k * 16 + ar) * SPITCH + np * 16 + ac]);
            mma16816(c[np * 2],     a0, a1, a2, a3, b0, b1);
            mma16816(c[np * 2 + 1], a0, a1, a2, a3, b2, b3);
        }
    }
}

// ---------------- fused GEMM per layer (HMMA): 128 thr, 64-row tile ----------
// 4 blocks/SM (16k regs, 27KB smem) -> 626 blocks ~ 1.06 waves, small tail.
// X0 != null (layer 0): pre-pass computes sA = relu(fp16(X0_tile) @ IW + ib).
__global__ __launch_bounds__(128, 4) void gemm4_kernel(
    const float* __restrict__ PW,    // 128x64 (head | tail)
    const float* __restrict__ AW,    // 64x64
    const float* __restrict__ RW,    // 64x64
    const float* __restrict__ pb,
    const float* __restrict__ ab,
    const float* __restrict__ rbv,
    const float* __restrict__ X0,
    const float* __restrict__ IW,
    const float* __restrict__ ib) {
    __shared__ __half sA[64 * SPITCH];      // 9.0 KB
    __shared__ __half sW[2][64 * SPITCH];   // 18.0 KB
    int t = threadIdx.x;
    int lane = t & 31, warp = t >> 5;        // 4 warps
    int warpm = warp * 16;
    int base = blockIdx.x * 64;
    int lq = lane & 3, lr = lane >> 2;

    if (X0) {
        // load rel_emb tile (fp32, guarded) -> fp16 sA; IW -> sW[0]
        #pragma unroll
        for (int i = 0; i < 8; i++) {
            int id = t + i * 128;             // 1024 float4 = 64 rows
            int row = id >> 4, c4 = id & 15;
            int gr = base + row;
            float4 w = (gr < R) ? ((const float4*)X0)[(size_t)gr * 16 + c4]
                                : make_float4(0.f, 0.f, 0.f, 0.f);
            cvt8(&sA[row * SPITCH + c4 * 4], w);
        }
        #pragma unroll
        for (int i = 0; i < 8; i++) {
            int id = t + i * 128;             // 1024 float4
            int row = id >> 4, c4 = id & 15;
            cvt8(&sW[0][row * SPITCH + c4 * 4], ((const float4*)IW)[id]);
        }
        __syncthreads();
        float c[8][4] = {};
        mma_one(c, sA, sW[0], warpm, lane);
        __syncthreads();   // all ldmatrix reads of sA done
        #pragma unroll
        for (int n = 0; n < 8; n++) {
            int col = n * 8 + lq * 2;
            float2 bi = ((const float2*)ib)[col >> 1];
            int r0 = warpm + lr;
            ((__half2*)&sA[r0 * SPITCH + col])[0] =
                __floats2half2_rn(fmaxf(c[n][0] + bi.x, 0.f), fmaxf(c[n][1] + bi.y, 0.f));
            ((__half2*)&sA[(r0 + 8) * SPITCH + col])[0] =
                __floats2half2_rn(fmaxf(c[n][2] + bi.x, 0.f), fmaxf(c[n][3] + bi.y, 0.f));
        }
        __syncthreads();
    } else {
        // load fp16 emb tile directly: 64 rows x 8 uint4 = 512 uint4
        #pragma unroll
        for (int i = 0; i < 4; i++) {
            int id = t + i * 128;
            int row = id >> 3, c8 = id & 7;
            *(uint4*)&sA[row * SPITCH + c8 * 8] =
                ((const uint4*)g_embh)[(size_t)base * 8 + id];
        }
    }
    // load PW: rows 0-63 -> sW[0], rows 64-127 -> sW[1]
    #pragma unroll
    for (int i = 0; i < 16; i++) {
        int id = t + i * 128;                 // 2048 float4 = 128 rows
        int row = id >> 4, c4 = id & 15;
        float4 w = ((const float4*)PW)[id];
        __half* d = (row < 64) ? &sW[0][row * SPITCH + c4 * 4]
                               : &sW[1][(row - 64) * SPITCH + c4 * 4];
        cvt8(d, w);
    }
    __syncthreads();

    __half2* H = (__half2*)g_attwh;

    // ---- pass 0: ahead (fp32, no bias) + atail (+pb, fp16 slot 0) ----
    {
        float c[2][8][4] = {};
        mma_dual(c, sA, sW[0], sW[1], warpm, lane);
        #pragma unroll
        for (int n = 0; n < 8; n++) {
            int col = n * 8 + lq * 2;
            size_t r0 = base + warpm + lr, r1 = r0 + 8;
            *(float2*)&g_ahead[r0 * 64 + col] = make_float2(c[0][n][0], c[0][n][1]);
            *(float2*)&g_ahead[r1 * 64 + col] = make_float2(c[0][n][2], c[0][n][3]);
            float2 bt = ((const float2*)pb)[col >> 1];
            H[r0 * 64 + col] = __floats2half2_rn(c[1][n][0] + bt.x, c[1][n][1] + bt.y);
            H[r1 * 64 + col] = __floats2half2_rn(c[1][n][2] + bt.x, c[1][n][3] + bt.y);
        }
    }
    __syncthreads();   // done reading sW
    // load AW -> sW[0], RW -> sW[1]
    #pragma unroll
    for (int i = 0; i < 8; i++) {
        int id = t + i * 128;
        int row = id >> 4, c4 = id & 15;
        cvt8(&sW[0][row * SPITCH + c4 * 4], ((const float4*)AW)[id]);
        cvt8(&sW[1][row * SPITCH + c4 * 4], ((const float4*)RW)[id]);
    }
    __syncthreads();
    // ---- pass 1: wtail (+ab, fp16 slot 1) + res (relu(+rb), fp32) ----
    {
        float c[2][8][4] = {};
        mma_dual(c, sA, sW[0], sW[1], warpm, lane);
        #pragma unroll
        for (int n = 0; n < 8; n++) {
            int col = n * 8 + lq * 2;
            size_t r0 = base + warpm + lr, r1 = r0 + 8;
            float2 ba = ((const float2*)ab)[col >> 1];
            float2 br = ((const float2*)rbv)[col >> 1];
            H[r0 * 64 + col + 1] = __floats2half2_rn(c[0][n][0] + ba.x, c[0][n][1] + ba.y);
            H[r1 * 64 + col + 1] = __floats2half2_rn(c[0][n][2] + ba.x, c[0][n][3] + ba.y);
            *(float2*)&g_res[r0 * 64 + col] =
                make_float2(fmaxf(c[1][n][0] + br.x, 0.f), fmaxf(c[1][n][1] + br.y, 0.f));
            *(float2*)&g_res[r1 * 64 + col] =
                make_float2(fmaxf(c[1][n][2] + br.x, 0.f), fmaxf(c[1][n][3] + br.y, 0.f));
        }
    }
}

// ---------------- attention: one warp per node, 4-deep batch, no-max softmax ----
// inner score math in half2 (fewer issue slots; scores |x|<~1 so half is safe)
__global__ void attn_kernel(const float* __restrict__ abin,
                            const float* __restrict__ avec,
                            float* outp) {
    __shared__ float s_abin[NBIN * HN];
    int t = threadIdx.x;
    if (t < NBIN * HN) s_abin[t] = lk(abin[t]);

    if (outp) {   // final layer: re-zero CSR scratch for next graph replay
        int g = blockIdx.x * blockDim.x + t;
        if (g < R) g_deg[g] = 0;
        if (g < NSB) g_pub[g] = 0;
    }
    __syncthreads();

    int warp = t >> 5, lane = t & 31;
    int r = blockIdx.x * 8 + warp;
    if (r >= R) return;

    int h = lane >> 2;
    float2 ahv = ((const float2*)g_ahead)[r * 32 + lane];
    __half2 ahv2 = __floats2half2_rn(ahv.x, ahv.y);
    __half2 av2 = __floats2half2_rn(avec[h * 8 + (lane & 3) * 2],
                                    avec[h * 8 + (lane & 3) * 2 + 1]);
    const __half2 c02 = __float2half2_rn(0.2f);
    const uint2* AWp = (const uint2*)g_attwh;

    float s = 0.f, a0 = 0.f, a1 = 0.f;
    int i = g_off[r], end = g_off[r + 1];

    while (i < end) {
        int n = end - i; if (n > 4) n = 4;
        uint2 v[4]; int bbs[4];
        #pragma unroll
        for (int j = 0; j < 4; j++) {
            if (j < n) {
                int etb = g_etb[i + j];
                bbs[j] = etb >> 20;
                v[j] = AWp[(size_t)(etb & 0xFFFFF) * 32 + lane];
            }
        }
        #pragma unroll
        for (int j = 0; j < 4; j++) {
            if (j < n) {
                __half2 at2 = *(const __half2*)&v[j].x;
                __half2 t2 = __hadd2(ahv2, at2);
                __half2 z2 = __hmax2(t2, __hmul2(t2, c02));   // leaky_relu(0.2)
                float2 pd = __half22float2(__hmul2(z2, av2));
                float p = pd.x + pd.y;
                p += __shfl_xor_sync(0xffffffffu, p, 1);
                p += __shfl_xor_sync(0xffffffffu, p, 2);
                float e = __expf(p + s_abin[bbs[j] * 8 + h]);
                float2 wt = __half22float2(*(const __half2*)&v[j].y);
                s  += e;
                a0 += e * wt.x;
                a1 += e * wt.y;
            }
        }
        i += 4;
    }
    float inv = 1.f / (s + 1e-16f);
    float o0 = fmaxf(a0 * inv, 0.f);
    float o1 = fmaxf(a1 * inv, 0.f);
    float2 rv = ((const float2*)g_res)[r * 32 + lane];
    float ox = o0 + rv.x;
    float oy = o1 + rv.y;
    if (outp)
        ((float2*)outp)[r * 32 + lane] = make_float2(ox, oy);
    else
        ((__half2*)g_embh)[r * 32 + lane] = __floats2half2_rn(ox, oy);
}

// ---------------- host ----------------
extern "C" void kernel_launch(void* const* d_in, const int* in_sizes, int n_in,
                              void* d_out, int out_size) {
    const int*   trip     = (const int*)d_in[0];
    const float* rel_emb  = (const float*)d_in[1];
    const float* p1w      = (const float*)d_in[2];
    const float* p1b      = (const float*)d_in[3];
    const float* apw      = (const float*)d_in[4];
    const float* apb      = (const float*)d_in[5];
    const float* abin     = (const float*)d_in[6];
    const float* avec     = (const float*)d_in[7];
    const float* agw      = (const float*)d_in[8];
    const float* agb      = (const float*)d_in[9];
    const float* rw       = (const float*)d_in[10];
    const float* rb       = (const float*)d_in[11];

    int E = in_sizes[0] / 3;
    if (E > EMAX) E = EMAX;

    const int TB = 256;
    int e4bl = ((E + 3) / 4 + TB - 1) / TB;

    // fork: CSR build on side stream, concurrent with layer-0 GEMM
    cudaEventRecord(g_sh.fork, 0);
    cudaStreamWaitEvent(g_sh.s, g_sh.fork, 0);
    hist_kernel<<<e4bl, TB, 0, g_sh.s>>>(trip, E);
    scan_kernel<<<NSB, 256, 0, g_sh.s>>>();
    scatter_kernel<<<e4bl, TB, 0, g_sh.s>>>(trip, E);
    cudaEventRecord(g_sh.join, g_sh.s);

    // main stream: layer-0 GEMM (independent of CSR)
    gemm4_kernel<<<RB, 128>>>(apw, agw, rw, apb, agb, rb,
                              rel_emb, p1w, p1b);

    // join before first attention (needs CSR + gemm outputs)
    cudaStreamWaitEvent(0, g_sh.join, 0);
    attn_kernel<<<R / 8, 256>>>(abin, avec, nullptr);

    // layer 1
    gemm4_kernel<<<RB, 128>>>(apw + 8192, agw + 4096, rw + 4096,
                              apb + 64, agb + 64, rb + 64,
                              nullptr, nullptr, nullptr);
    attn_kernel<<<R / 8, 256>>>(abin + NBIN * HN, avec + HN * 8,
                                (float*)d_out);
}